// round 7
// baseline (speedup 1.0000x reference)
#include <cuda_runtime.h>
#include <cuda_bf16.h>

// SpanIndexEncoder: out[t] = sum over nodes n (n<num_nodes, s_n<=t<=e_n) of emb[n]
// Sparse boundary events + QUARTER-granularity (4-token) global scan:
//   A: classify events into per-chunk (16-token) lists        (cheap scalar atomics)
//   B: per-quarter sums: gather signed event rows, one pass   (2048 quarter entries)
//   C: warp-per-feature exclusive scan over 2048 quarter sums
//   D: apply: run_k = quarter prefix + predicated adds of own-quarter events; store 4 rows.
//      No bulk smem, no sort, no cross-thread chain -> high occupancy, full gather MLP.
//   D self-resets g_cnt -> no memset node (device globals zero-init at module load).

#define MAX_TOKENS 8192
#define MAX_NODES  8192
#define FEAT       256
#define F4         (FEAT / 4)            // 64 float4 columns
#define CHUNK      16
#define NCHUNK     (MAX_TOKENS / CHUNK)  // 512
#define NQ         (NCHUNK * 4)          // 2048 quarters
#define CAP        16384                 // worst-case events per chunk
#define SW_CAP     1024                  // staged event words per chunk (4 KB)

// event word: bits[0:13)=node, bits[13:17)=token-within-chunk, bit 17=sign(1=minus)
__device__ unsigned g_ev[NCHUNK * CAP];
__device__ int      g_cnt[NCHUNK];       // self-resetting
__device__ float    g_q[NQ * FEAT];      // quarter sums -> exclusive quarter prefixes

// ---- A: classify span boundaries into per-chunk lists ----
__global__ void __launch_bounds__(256) classify_kernel(
    const int* __restrict__ starts,
    const int* __restrict__ ends,
    const int* __restrict__ num_nodes_p)
{
    const int n = blockIdx.x * 256 + threadIdx.x;
    if (n >= num_nodes_p[0]) return;
    const int s = starts[n];
    const int e = ends[n];
    if (s > e) return;

    int p = atomicAdd(&g_cnt[s >> 4], 1);
    g_ev[(s >> 4) * CAP + p] = (unsigned)n | ((unsigned)(s & 15) << 13);

    const int e1 = e + 1;
    if (e1 < MAX_TOKENS) {
        p = atomicAdd(&g_cnt[e1 >> 4], 1);
        g_ev[(e1 >> 4) * CAP + p] = (unsigned)n | ((unsigned)(e1 & 15) << 13) | (1u << 17);
    }
}

// ---- B: per-quarter sums. 512 blocks x 256 thr: thread (q=tid>>6, j=tid&63) ----
__global__ void __launch_bounds__(256) qsum_kernel(const float* __restrict__ emb)
{
    const int c   = blockIdx.x;
    const int tid = threadIdx.x;
    const int j   = tid & 63;
    const int q   = tid >> 6;

    __shared__ unsigned sw[SW_CAP];
    int cnt = g_cnt[c]; if (cnt > CAP) cnt = CAP;
    const int sc = cnt < SW_CAP ? cnt : SW_CAP;
    for (int e = tid; e < sc; e += 256) sw[e] = g_ev[c * CAP + e];
    __syncthreads();

    const float4* emb4 = reinterpret_cast<const float4*>(emb);
    float4 s = make_float4(0.f, 0.f, 0.f, 0.f);
    for (int e = 0; e < cnt; ++e) {
        const unsigned w = (e < SW_CAP) ? sw[e] : g_ev[c * CAP + e];
        const int tok = (w >> 13) & 15;
        if ((tok >> 2) != q) continue;                 // uniform across the warp
        const float sg = (w & (1u << 17)) ? -1.f : 1.f;
        const float4 v = emb4[(size_t)(w & 8191u) * F4 + j];
        s.x += sg * v.x; s.y += sg * v.y; s.z += sg * v.z; s.w += sg * v.w;
    }
    *reinterpret_cast<float4*>(&g_q[(size_t)(c * 4 + q) * FEAT + (j << 2)]) = s;
}

// ---- C: warp-per-feature exclusive scan over NQ=2048 quarter sums ----
__global__ void __launch_bounds__(32) qscan_kernel()
{
    const int f = blockIdx.x;
    const int l = threadIdx.x;
    const int base = l * 64;

    float v[64];
#pragma unroll
    for (int i = 0; i < 64; ++i) v[i] = g_q[(size_t)(base + i) * FEAT + f];
#pragma unroll
    for (int i = 1; i < 64; ++i) v[i] += v[i - 1];

    const float own = v[63];
    float incl = own;
#pragma unroll
    for (int d = 1; d < 32; d <<= 1) {
        const float t = __shfl_up_sync(0xffffffffu, incl, d);
        if (l >= d) incl += t;
    }
    const float excl = incl - own;

    g_q[(size_t)(base + 0) * FEAT + f] = excl;
#pragma unroll
    for (int i = 1; i < 64; ++i)
        g_q[(size_t)(base + i) * FEAT + f] = excl + v[i - 1];
}

// ---- D: apply. 512 blocks x 256 thr: thread (q, j) owns 4 tokens x 1 float4 col ----
__global__ void __launch_bounds__(256) apply_kernel(
    const float* __restrict__ emb,
    float*       __restrict__ out)
{
    const int c   = blockIdx.x;
    const int tid = threadIdx.x;
    const int j   = tid & 63;
    const int q   = tid >> 6;

    __shared__ unsigned sw[SW_CAP];
    int cnt = g_cnt[c]; if (cnt > CAP) cnt = CAP;
    const int sc = cnt < SW_CAP ? cnt : SW_CAP;
    for (int e = tid; e < sc; e += 256) sw[e] = g_ev[c * CAP + e];
    __syncthreads();

    const float4* emb4 = reinterpret_cast<const float4*>(emb);

    // run_k for tokens 4q+k; all start at the global quarter prefix
    const float4 pref = *reinterpret_cast<const float4*>(
        &g_q[(size_t)(c * 4 + q) * FEAT + (j << 2)]);
    float4 r0 = pref, r1 = pref, r2 = pref, r3 = pref;

    for (int e = 0; e < cnt; ++e) {
        const unsigned w = (e < SW_CAP) ? sw[e] : g_ev[c * CAP + e];
        const int tok = (w >> 13) & 15;
        if ((tok >> 2) != q) continue;                 // uniform across the warp
        const int tl = tok & 3;
        const float sg = (w & (1u << 17)) ? -1.f : 1.f;
        const float4 v = emb4[(size_t)(w & 8191u) * F4 + j];
        const float s0 = (tl <= 0) ? sg : 0.f;
        const float s1 = (tl <= 1) ? sg : 0.f;
        const float s2 = (tl <= 2) ? sg : 0.f;
        const float s3 = (tl <= 3) ? sg : 0.f;
        r0.x += s0 * v.x; r0.y += s0 * v.y; r0.z += s0 * v.z; r0.w += s0 * v.w;
        r1.x += s1 * v.x; r1.y += s1 * v.y; r1.z += s1 * v.z; r1.w += s1 * v.w;
        r2.x += s2 * v.x; r2.y += s2 * v.y; r2.z += s2 * v.z; r2.w += s2 * v.w;
        r3.x += s3 * v.x; r3.y += s3 * v.y; r3.z += s3 * v.z; r3.w += s3 * v.w;
    }

    float4* o = reinterpret_cast<float4*>(out + (size_t)(c * CHUNK + q * 4) * FEAT + (j << 2));
    o[0 * F4] = r0;
    o[1 * F4] = r1;
    o[2 * F4] = r2;
    o[3 * F4] = r3;

    // self-reset for next graph replay (all reads of g_cnt done by every thread above)
    __syncthreads();
    if (tid == 0) g_cnt[c] = 0;
}

extern "C" void kernel_launch(void* const* d_in, const int* in_sizes, int n_in,
                              void* d_out, int out_size)
{
    const float* emb    = (const float*)d_in[0];
    const int*   starts = (const int*)d_in[1];
    const int*   ends   = (const int*)d_in[2];
    const int*   nnp    = (const int*)d_in[3];
    float*       out    = (float*)d_out;

    classify_kernel<<<MAX_NODES / 256, 256>>>(starts, ends, nnp);
    qsum_kernel<<<NCHUNK, 256>>>(emb);
    qscan_kernel<<<FEAT, 32>>>();
    apply_kernel<<<NCHUNK, 256>>>(emb, out);
}

// round 8
// speedup vs baseline: 1.2912x; 1.2912x over previous
#include <cuda_runtime.h>
#include <cuda_bf16.h>

// SpanIndexEncoder: out[t] = sum over nodes n (n<num_nodes, s_n<=t<=e_n) of emb[n]
// Sparse boundary events, classified into PER-QUARTER (4-token) lists so the hot
// kernels run short, contiguous, BRANCH-FREE gather loops with batched MLP:
//   A: classify events into per-quarter lists (scalar atomics, ~2 per node)
//   B: per-quarter sums: batched gather of own-quarter signed rows
//   C: warp-per-feature exclusive scan over 2048 quarter sums
//   D: apply: 4 token accumulators, predicated adds of own-quarter events; store 4 rows
//   D self-resets counters -> no memset node (device globals zero-init at load).

#define MAX_TOKENS 8192
#define MAX_NODES  8192
#define FEAT       256
#define F4         (FEAT / 4)        // 64 float4 columns
#define NQ         (MAX_TOKENS / 4)  // 2048 quarters
#define NCHUNK     (MAX_TOKENS / 16) // 512 apply blocks (4 quarters each)
#define CAP_Q      16384             // absolute worst case events in one quarter

// event word: bits[0:13)=node, bits[13:15)=token-within-quarter, bit15=sign(1=minus)
__device__ unsigned g_qev[(size_t)NQ * CAP_Q];
__device__ int      g_qcnt[NQ];          // self-resetting
__device__ float    g_q[NQ * FEAT];      // quarter sums -> exclusive prefixes

// ---- A: classify span boundaries into per-quarter lists ----
__global__ void __launch_bounds__(256) classify_kernel(
    const int* __restrict__ starts,
    const int* __restrict__ ends,
    const int* __restrict__ num_nodes_p)
{
    const int n = blockIdx.x * 256 + threadIdx.x;
    if (n >= num_nodes_p[0]) return;
    const int s = starts[n];
    const int e = ends[n];
    if (s > e) return;

    int q = s >> 2;
    int p = atomicAdd(&g_qcnt[q], 1);
    g_qev[(size_t)q * CAP_Q + p] = (unsigned)n | ((unsigned)(s & 3) << 13);

    const int e1 = e + 1;
    if (e1 < MAX_TOKENS) {
        q = e1 >> 2;
        p = atomicAdd(&g_qcnt[q], 1);
        g_qev[(size_t)q * CAP_Q + p] = (unsigned)n | ((unsigned)(e1 & 3) << 13) | (1u << 15);
    }
}

__device__ __forceinline__ float4 sgn_row(const float4* emb4, unsigned w, int j) {
    const float sg = (w & (1u << 15)) ? -1.f : 1.f;
    const float4 v = emb4[(size_t)(w & 8191u) * F4 + j];
    return make_float4(sg * v.x, sg * v.y, sg * v.z, sg * v.w);
}

// ---- B: per-quarter sums. 512 blocks x 256 thr: thread (q=tid>>6, j=tid&63) ----
__global__ void __launch_bounds__(256) qsum_kernel(const float* __restrict__ emb)
{
    const int tid = threadIdx.x;
    const int j   = tid & 63;
    const int qi  = blockIdx.x * 4 + (tid >> 6);

    const int cnt = g_qcnt[qi];
    const unsigned* evq = g_qev + (size_t)qi * CAP_Q;
    const float4* emb4 = reinterpret_cast<const float4*>(emb);

    float4 s = make_float4(0.f, 0.f, 0.f, 0.f);
    int i = 0;
    for (; i + 4 <= cnt; i += 4) {   // batched: 4 words then 4 gathers, all independent
        const unsigned w0 = evq[i], w1 = evq[i + 1], w2 = evq[i + 2], w3 = evq[i + 3];
        const float4 a = sgn_row(emb4, w0, j);
        const float4 b = sgn_row(emb4, w1, j);
        const float4 c = sgn_row(emb4, w2, j);
        const float4 d = sgn_row(emb4, w3, j);
        s.x += (a.x + b.x) + (c.x + d.x);
        s.y += (a.y + b.y) + (c.y + d.y);
        s.z += (a.z + b.z) + (c.z + d.z);
        s.w += (a.w + b.w) + (c.w + d.w);
    }
    for (; i < cnt; ++i) {
        const float4 a = sgn_row(emb4, evq[i], j);
        s.x += a.x; s.y += a.y; s.z += a.z; s.w += a.w;
    }
    *reinterpret_cast<float4*>(&g_q[(size_t)qi * FEAT + (j << 2)]) = s;
}

// ---- C: warp-per-feature exclusive scan over NQ=2048 quarter sums ----
__global__ void __launch_bounds__(32) qscan_kernel()
{
    const int f = blockIdx.x;
    const int l = threadIdx.x;
    const int base = l * 64;

    float v[64];
#pragma unroll
    for (int i = 0; i < 64; ++i) v[i] = g_q[(size_t)(base + i) * FEAT + f];
#pragma unroll
    for (int i = 1; i < 64; ++i) v[i] += v[i - 1];

    const float own = v[63];
    float incl = own;
#pragma unroll
    for (int d = 1; d < 32; d <<= 1) {
        const float t = __shfl_up_sync(0xffffffffu, incl, d);
        if (l >= d) incl += t;
    }
    const float excl = incl - own;

    g_q[(size_t)(base + 0) * FEAT + f] = excl;
#pragma unroll
    for (int i = 1; i < 64; ++i)
        g_q[(size_t)(base + i) * FEAT + f] = excl + v[i - 1];
}

// ---- D: apply. 512 blocks x 256 thr: thread (q, j) owns 4 tokens x 1 float4 col ----
__global__ void __launch_bounds__(256) apply_kernel(
    const float* __restrict__ emb,
    float*       __restrict__ out)
{
    const int c   = blockIdx.x;
    const int tid = threadIdx.x;
    const int j   = tid & 63;
    const int q   = tid >> 6;
    const int qi  = c * 4 + q;

    const int cnt = g_qcnt[qi];
    const unsigned* evq = g_qev + (size_t)qi * CAP_Q;
    const float4* emb4 = reinterpret_cast<const float4*>(emb);

    const float4 pref = *reinterpret_cast<const float4*>(&g_q[(size_t)qi * FEAT + (j << 2)]);
    float4 r0 = pref, r1 = pref, r2 = pref, r3 = pref;

    int i = 0;
    for (; i + 2 <= cnt; i += 2) {   // batched pairs: independent word + row loads
        const unsigned wa = evq[i], wb = evq[i + 1];
        const float4 va = sgn_row(emb4, wa, j);
        const float4 vb = sgn_row(emb4, wb, j);
        const int ta = (wa >> 13) & 3, tb = (wb >> 13) & 3;
        const float a1 = (ta <= 1) ? 1.f : 0.f, a2 = (ta <= 2) ? 1.f : 0.f;
        const float b1 = (tb <= 1) ? 1.f : 0.f, b2 = (tb <= 2) ? 1.f : 0.f;
        const float a0 = (ta == 0) ? 1.f : 0.f, b0 = (tb == 0) ? 1.f : 0.f;
        r0.x += a0 * va.x + b0 * vb.x;  r0.y += a0 * va.y + b0 * vb.y;
        r0.z += a0 * va.z + b0 * vb.z;  r0.w += a0 * va.w + b0 * vb.w;
        r1.x += a1 * va.x + b1 * vb.x;  r1.y += a1 * va.y + b1 * vb.y;
        r1.z += a1 * va.z + b1 * vb.z;  r1.w += a1 * va.w + b1 * vb.w;
        r2.x += a2 * va.x + b2 * vb.x;  r2.y += a2 * va.y + b2 * vb.y;
        r2.z += a2 * va.z + b2 * vb.z;  r2.w += a2 * va.w + b2 * vb.w;
        r3.x += va.x + vb.x;            r3.y += va.y + vb.y;
        r3.z += va.z + vb.z;            r3.w += va.w + vb.w;
    }
    for (; i < cnt; ++i) {
        const unsigned w = evq[i];
        const float4 v = sgn_row(emb4, w, j);
        const int tl = (w >> 13) & 3;
        const float s0 = (tl == 0) ? 1.f : 0.f;
        const float s1 = (tl <= 1) ? 1.f : 0.f;
        const float s2 = (tl <= 2) ? 1.f : 0.f;
        r0.x += s0 * v.x; r0.y += s0 * v.y; r0.z += s0 * v.z; r0.w += s0 * v.w;
        r1.x += s1 * v.x; r1.y += s1 * v.y; r1.z += s1 * v.z; r1.w += s1 * v.w;
        r2.x += s2 * v.x; r2.y += s2 * v.y; r2.z += s2 * v.z; r2.w += s2 * v.w;
        r3.x += v.x;      r3.y += v.y;      r3.z += v.z;      r3.w += v.w;
    }

    float4* o = reinterpret_cast<float4*>(out + (size_t)(c * 16 + q * 4) * FEAT + (j << 2));
    o[0 * F4] = r0;
    o[1 * F4] = r1;
    o[2 * F4] = r2;
    o[3 * F4] = r3;

    // self-reset for next graph replay (every thread has consumed cnt above)
    __syncthreads();
    if (tid < 4) g_qcnt[c * 4 + tid] = 0;
}

extern "C" void kernel_launch(void* const* d_in, const int* in_sizes, int n_in,
                              void* d_out, int out_size)
{
    const float* emb    = (const float*)d_in[0];
    const int*   starts = (const int*)d_in[1];
    const int*   ends   = (const int*)d_in[2];
    const int*   nnp    = (const int*)d_in[3];
    float*       out    = (float*)d_out;

    classify_kernel<<<MAX_NODES / 256, 256>>>(starts, ends, nnp);
    qsum_kernel<<<NQ / 4, 256>>>(emb);
    qscan_kernel<<<FEAT, 32>>>();
    apply_kernel<<<NCHUNK, 256>>>(emb, out);
}